// round 2
// baseline (speedup 1.0000x reference)
#include <cuda_runtime.h>

#define N_NODES 8192
#define F_DIM   256
#define E_EDGES 262144
#define ADJ_ROW_WORDS (N_NODES / 32)              // 256
#define ADJ_WORDS     (N_NODES * ADJ_ROW_WORDS)   // 2,097,152 words = 8MB

// ---------------- scratch (device globals; no allocation allowed) ----------
__device__ int      g_is32;                       // 1 if integer inputs are int32
__device__ int      g_ei[2 * E_EDGES];            // normalized edge index (int32)
__device__ float    g_mean[F_DIM];
__device__ float    g_w[N_NODES];
__device__ float    g_cov[F_DIM * F_DIM];
__device__ float    g_cor[F_DIM * F_DIM];
__device__ float    g_z2[N_NODES * F_DIM];        // 8 MB
__device__ float    g_nrm[N_NODES];
__device__ unsigned g_adj[ADJ_WORDS];             // 8 MB bitmask
__device__ float    g_scores[N_NODES];
__device__ float    g_deg[N_NODES];
__device__ double   g_penalty;

// ---------------- dtype detection ------------------------------------------
__global__ void detect_kernel(const void* __restrict__ ei_raw) {
    // Interpret first 128 entries as int64. If data is really int32, the high
    // word of each "int64" is a random node id (< 8192 but nonzero w.h.p.),
    // so some value falls outside [0, N). All-int64 valid data stays in range.
    const long long* p = (const long long*)ei_raw;
    int bad = 0;
    for (int k = 0; k < 128; k++) {
        long long v = p[k];
        if (v < 0 || v >= N_NODES) bad = 1;
    }
    g_is32 = bad;
}

// ---------------- normalize edges to int32 ---------------------------------
__global__ void convert_kernel(const void* __restrict__ ei_raw) {
    int idx = blockIdx.x * blockDim.x + threadIdx.x;
    if (idx >= 2 * E_EDGES) return;
    int v;
    if (g_is32) v = ((const int*)ei_raw)[idx];
    else        v = (int)((const long long*)ei_raw)[idx];
    // clamp defensively (no-op for valid data)
    v = min(max(v, 0), N_NODES - 1);
    g_ei[idx] = v;
}

// ---------------- zero scratch ---------------------------------------------
__global__ void zero_kernel() {
    int i = blockIdx.x * blockDim.x + threadIdx.x;
    int stride = gridDim.x * blockDim.x;
    for (int idx = i; idx < ADJ_WORDS; idx += stride) g_adj[idx] = 0u;
    for (int idx = i; idx < F_DIM * F_DIM; idx += stride) g_cov[idx] = 0.f;
    if (i < F_DIM) g_mean[i] = 0.f;
    if (i < N_NODES) { g_scores[i] = 0.f; g_deg[i] = 0.f; }
    if (i == 0) g_penalty = 0.0;
}

// ---------------- column sums (-> mean) ------------------------------------
__global__ void mean_kernel(const float* __restrict__ z) {
    int f = threadIdx.x;                 // 256 threads = one per feature
    int r0 = blockIdx.x * 128;           // 64 blocks x 128 rows
    float acc = 0.f;
    for (int r = 0; r < 128; r++) acc += z[(r0 + r) * F_DIM + f];
    atomicAdd(&g_mean[f], acc);
}

// ---------------- scale mean, compute per-node weight w --------------------
__global__ void prep_kernel(const void* __restrict__ k2u_raw,
                            const void* __restrict__ u2k_raw) {
    int i = blockIdx.x * blockDim.x + threadIdx.x;
    if (i < F_DIM) g_mean[i] *= (1.f / (float)N_NODES);
    if (i < N_NODES) {
        float fa, fb;
        if (g_is32) {
            fa = (float)((const int*)k2u_raw)[i];
            fb = (float)((const int*)u2k_raw)[i];
        } else {
            fa = (float)((const long long*)k2u_raw)[i];
            fb = (float)((const long long*)u2k_raw)[i];
        }
        float a = powf(0.9f, fa);
        float b = powf(0.9f, fb);
        g_w[i] = a + 1.f - b;
    }
}

// ---------------- cov = zm^T zm  (F x F, K = N, split-K=4) -----------------
__global__ void cov_kernel(const float* __restrict__ z) {
    __shared__ float A[32][33];
    __shared__ float B[32][33];
    __shared__ float ma[32], mb[32];
    int a0 = blockIdx.y * 32, b0 = blockIdx.x * 32;
    int t = threadIdx.x;
    if (t < 32) ma[t] = g_mean[a0 + t];
    else if (t < 64) mb[t - 32] = g_mean[b0 + t - 32];
    __syncthreads();

    float acc00 = 0.f, acc01 = 0.f, acc10 = 0.f, acc11 = 0.f;
    int r0 = blockIdx.z * (N_NODES / 4);
    int tx = t & 15, ty = t >> 4;
    for (int rc = 0; rc < N_NODES / 4; rc += 32) {
#pragma unroll
        for (int q = 0; q < 4; q++) {
            int idx = t + q * 256;
            int rr = idx >> 5, cc = idx & 31;
            int gr = r0 + rc + rr;
            A[rr][cc] = z[gr * F_DIM + a0 + cc] - ma[cc];
            B[rr][cc] = z[gr * F_DIM + b0 + cc] - mb[cc];
        }
        __syncthreads();
#pragma unroll
        for (int kk = 0; kk < 32; kk++) {
            float av0 = A[kk][ty * 2], av1 = A[kk][ty * 2 + 1];
            float bv0 = B[kk][tx * 2], bv1 = B[kk][tx * 2 + 1];
            acc00 += av0 * bv0; acc01 += av0 * bv1;
            acc10 += av1 * bv0; acc11 += av1 * bv1;
        }
        __syncthreads();
    }
    atomicAdd(&g_cov[(a0 + ty * 2 + 0) * F_DIM + b0 + tx * 2 + 0], acc00);
    atomicAdd(&g_cov[(a0 + ty * 2 + 0) * F_DIM + b0 + tx * 2 + 1], acc01);
    atomicAdd(&g_cov[(a0 + ty * 2 + 1) * F_DIM + b0 + tx * 2 + 0], acc10);
    atomicAdd(&g_cov[(a0 + ty * 2 + 1) * F_DIM + b0 + tx * 2 + 1], acc11);
}

// ---------------- correlation matrix ---------------------------------------
__global__ void cor_kernel() {
    int a = blockIdx.x, b = threadIdx.x;
    float denom = sqrtf(g_cov[a * F_DIM + a]) * sqrtf(g_cov[b * F_DIM + b]);
    float v = g_cov[a * F_DIM + b] / denom;
    if (isnan(v)) v = 0.f;                     // nan_to_num
    v = fminf(1.f, fmaxf(-1.f, v));            // clip (also handles +-inf)
    if (a == b) v = 0.f;                       // fill_diagonal_(0)
    g_cor[a * F_DIM + b] = v;
}

// ---------------- z2 = z + EPS * (w .* zm) @ cor ---------------------------
__global__ void z2_kernel(const float* __restrict__ z) {
    __shared__ float Ws[16][68];
    __shared__ float Cs[16][68];
    int r0 = blockIdx.y * 64, c0 = blockIdx.x * 64;
    int t = threadIdx.x;
    int tx = t & 15, ty = t >> 4;
    float acc[4][4] = {};
    for (int k0 = 0; k0 < F_DIM; k0 += 16) {
#pragma unroll
        for (int q = 0; q < 4; q++) {
            int idx = t + q * 256;                 // 0..1023
            int row = idx >> 4, kk = idx & 15;
            Ws[kk][row] = g_w[r0 + row] *
                (z[(r0 + row) * F_DIM + k0 + kk] - g_mean[k0 + kk]);
            int kk2 = idx >> 6, cc = idx & 63;
            Cs[kk2][cc] = g_cor[(k0 + kk2) * F_DIM + c0 + cc];
        }
        __syncthreads();
#pragma unroll
        for (int kk = 0; kk < 16; kk++) {
            float4 av = *(const float4*)&Ws[kk][ty * 4];
            float4 bv = *(const float4*)&Cs[kk][tx * 4];
            float a4[4] = {av.x, av.y, av.z, av.w};
            float b4[4] = {bv.x, bv.y, bv.z, bv.w};
#pragma unroll
            for (int i = 0; i < 4; i++)
#pragma unroll
                for (int j = 0; j < 4; j++)
                    acc[i][j] += a4[i] * b4[j];
        }
        __syncthreads();
    }
#pragma unroll
    for (int i = 0; i < 4; i++)
#pragma unroll
        for (int j = 0; j < 4; j++) {
            int r = r0 + ty * 4 + i, c = c0 + tx * 4 + j;
            g_z2[r * F_DIM + c] = z[r * F_DIM + c] + 0.01f * acc[i][j];
        }
}

// ---------------- per-node L2 norm of z2 -----------------------------------
__global__ void norm_kernel() {
    int n = blockIdx.x;
    int t = threadIdx.x;                      // 64 threads
    float4 v = *(const float4*)&g_z2[n * F_DIM + t * 4];
    float s = v.x * v.x + v.y * v.y + v.z * v.z + v.w * v.w;
#pragma unroll
    for (int o = 16; o; o >>= 1) s += __shfl_down_sync(0xffffffffu, s, o);
    __shared__ float sw[2];
    if ((t & 31) == 0) sw[t >> 5] = s;
    __syncthreads();
    if (t == 0) g_nrm[n] = fmaxf(sqrtf(sw[0] + sw[1]), 1e-8f);
}

// ---------------- adjacency bitmask from edges -----------------------------
__global__ void adj_kernel() {
    int e = blockIdx.x * blockDim.x + threadIdx.x;
    if (e >= E_EDGES) return;
    int i = g_ei[e];
    int j = g_ei[E_EDGES + e];
    atomicOr(&g_adj[i * ADJ_ROW_WORDS + (j >> 5)], 1u << (j & 31));
    atomicOr(&g_adj[j * ADJ_ROW_WORDS + (i >> 5)], 1u << (i & 31));
}

// ---------------- per-edge cosine, scatter by source -----------------------
__global__ void edge_kernel() {
    int warp = (blockIdx.x * blockDim.x + threadIdx.x) >> 5;
    int lane = threadIdx.x & 31;
    if (warp >= E_EDGES) return;
    int i = g_ei[warp];
    int j = g_ei[E_EDGES + warp];
    const float* zi = g_z2 + i * F_DIM;
    const float* zj = g_z2 + j * F_DIM;
    float acc = 0.f;
#pragma unroll
    for (int q = 0; q < 8; q++) {
        int f = lane + q * 32;
        acc += zi[f] * zj[f];
    }
#pragma unroll
    for (int o = 16; o; o >>= 1) acc += __shfl_down_sync(0xffffffffu, acc, o);
    if (lane == 0) {
        float sim = acc / (g_nrm[i] * g_nrm[j]);
        atomicAdd(&g_scores[i], sim);
        atomicAdd(&g_deg[i], 1.0f);
    }
}

// ---------------- big GEMM z2 @ z2^T with fused masked-threshold sum -------
// Symmetric: only tiles rb <= cb; off-diagonal tiles weighted x2.
__global__ void __launch_bounds__(256, 2) penalty_kernel() {
    int cb = blockIdx.x, rb = blockIdx.y;
    if (rb > cb) return;

    __shared__ float As[2][8][132];
    __shared__ float Bs[2][8][132];
    __shared__ unsigned adjS[128][4];
    __shared__ float red[8];

    int t = threadIdx.x;
    int tx = t & 15, ty = t >> 4;
    int r0 = rb * 128, c0 = cb * 128;
    int lr = t >> 1;                   // row within tile 0..127
    int lh = (t & 1) * 4;              // 4-float half of the 8-wide k-chunk

    float acc[8][8] = {};

    // chunk 0
    {
        float4 a = *(const float4*)&g_z2[(r0 + lr) * F_DIM + lh];
        float4 b = *(const float4*)&g_z2[(c0 + lr) * F_DIM + lh];
        As[0][lh + 0][lr] = a.x; As[0][lh + 1][lr] = a.y;
        As[0][lh + 2][lr] = a.z; As[0][lh + 3][lr] = a.w;
        Bs[0][lh + 0][lr] = b.x; Bs[0][lh + 1][lr] = b.y;
        Bs[0][lh + 2][lr] = b.z; Bs[0][lh + 3][lr] = b.w;
    }
    __syncthreads();

    for (int ch = 0; ch < 32; ch++) {
        int cur = ch & 1;
        float4 na, nb;
        if (ch < 31) {
            int k0 = (ch + 1) * 8;
            na = *(const float4*)&g_z2[(r0 + lr) * F_DIM + k0 + lh];
            nb = *(const float4*)&g_z2[(c0 + lr) * F_DIM + k0 + lh];
        }
#pragma unroll
        for (int kk = 0; kk < 8; kk++) {
            float4 a0 = *(const float4*)&As[cur][kk][ty * 8];
            float4 a1 = *(const float4*)&As[cur][kk][ty * 8 + 4];
            float4 b0 = *(const float4*)&Bs[cur][kk][tx * 8];
            float4 b1 = *(const float4*)&Bs[cur][kk][tx * 8 + 4];
            float av[8] = {a0.x, a0.y, a0.z, a0.w, a1.x, a1.y, a1.z, a1.w};
            float bv[8] = {b0.x, b0.y, b0.z, b0.w, b1.x, b1.y, b1.z, b1.w};
#pragma unroll
            for (int i = 0; i < 8; i++)
#pragma unroll
                for (int j = 0; j < 8; j++)
                    acc[i][j] += av[i] * bv[j];
        }
        if (ch < 31) {
            int nxt = cur ^ 1;
            As[nxt][lh + 0][lr] = na.x; As[nxt][lh + 1][lr] = na.y;
            As[nxt][lh + 2][lr] = na.z; As[nxt][lh + 3][lr] = na.w;
            Bs[nxt][lh + 0][lr] = nb.x; Bs[nxt][lh + 1][lr] = nb.y;
            Bs[nxt][lh + 2][lr] = nb.z; Bs[nxt][lh + 3][lr] = nb.w;
            __syncthreads();
        }
    }

    // adjacency words for this tile
#pragma unroll
    for (int q = 0; q < 2; q++) {
        int idx = t + q * 256;
        int row = idx >> 2, w = idx & 3;
        adjS[row][w] = g_adj[(r0 + row) * ADJ_ROW_WORDS + cb * 4 + w];
    }
    __syncthreads();

    float psum = 0.f;
#pragma unroll
    for (int i = 0; i < 8; i++) {
        int mi = ty * 8 + i;
#pragma unroll
        for (int j = 0; j < 8; j++) {
            int nj = tx * 8 + j;
            unsigned wbits = adjS[mi][nj >> 5];
            bool isadj = (wbits >> (nj & 31)) & 1u;
            float v = acc[i][j];
            if (!isadj && v > 0.8f) psum += v;
        }
    }
#pragma unroll
    for (int o = 16; o; o >>= 1) psum += __shfl_down_sync(0xffffffffu, psum, o);
    if ((t & 31) == 0) red[t >> 5] = psum;
    __syncthreads();
    if (t == 0) {
        float s = 0.f;
#pragma unroll
        for (int q = 0; q < 8; q++) s += red[q];
        double wgt = (rb == cb) ? 1.0 : 2.0;
        atomicAdd(&g_penalty, (double)s * wgt);
    }
}

// ---------------- finalize --------------------------------------------------
__global__ void final_kernel(float* __restrict__ out) {
    int t = threadIdx.x;
    float acc = 0.f;
    for (int n = t; n < N_NODES; n += 256) {
        float d = g_deg[n];
        if (d == 0.f) d = 1.f;
        acc += g_scores[n] / d;
    }
#pragma unroll
    for (int o = 16; o; o >>= 1) acc += __shfl_down_sync(0xffffffffu, acc, o);
    __shared__ float red[8];
    if ((t & 31) == 0) red[t >> 5] = acc;
    __syncthreads();
    if (t == 0) {
        float tot = 0.f;
        for (int q = 0; q < 8; q++) tot += red[q];
        double hom = -(double)tot / (double)N_NODES;
        double pen = g_penalty / ((double)N_NODES * (double)N_NODES);
        out[0] = (float)(hom + pen);
    }
}

// ---------------- launch ----------------------------------------------------
extern "C" void kernel_launch(void* const* d_in, const int* in_sizes, int n_in,
                              void* d_out, int out_size) {
    const float* z       = (const float*)d_in[0];
    // d_in[1] = x_hat (unused by reference)
    const void*  ei_raw  = d_in[2];
    const void*  k2u_raw = d_in[3];
    const void*  u2k_raw = d_in[4];
    float* out = (float*)d_out;

    detect_kernel<<<1, 1>>>(ei_raw);
    convert_kernel<<<(2 * E_EDGES + 255) / 256, 256>>>(ei_raw);
    zero_kernel<<<4096, 256>>>();
    mean_kernel<<<64, 256>>>(z);
    prep_kernel<<<32, 256>>>(k2u_raw, u2k_raw);
    cov_kernel<<<dim3(8, 8, 4), 256>>>(z);
    cor_kernel<<<256, 256>>>();
    z2_kernel<<<dim3(4, 128), 256>>>(z);
    norm_kernel<<<N_NODES, 64>>>();
    adj_kernel<<<E_EDGES / 256, 256>>>();
    edge_kernel<<<E_EDGES * 32 / 256, 256>>>();
    penalty_kernel<<<dim3(64, 64), 256>>>();
    final_kernel<<<1, 256>>>(out);
}